// round 16
// baseline (speedup 1.0000x reference)
#include <cuda_runtime.h>
#include <cuda_fp16.h>
#include <cstdint>

#define N_NODES  50000
#define N_EDGES  1600000
#define IN_FEAT  256
#define HID      128
#define OUT_FEAT 256
#define N_YZ     256              // [y | z] width

// ---------------------------------------------------------------------------
// Device scratch
// ---------------------------------------------------------------------------
__device__ __half g_y16 [N_NODES * HID];         // y fp16 (12.8 MB)
__device__ float  g_z   [N_NODES * HID];         // z fp32 (25.6 MB)
__device__ __half g_xh  [N_NODES * IN_FEAT];     // x split hi
__device__ __half g_xl  [N_NODES * IN_FEAT];     // x split lo
__device__ __half g_hh  [N_NODES * HID];         // h split hi
__device__ __half g_hl  [N_NODES * HID];         // h split lo
__device__ __half g_W1th[N_YZ * IN_FEAT];        // [We|Wn]^T hi  [256][256]
__device__ __half g_W1tl[N_YZ * IN_FEAT];        // [We|Wn]^T lo
__device__ __half g_W2th[OUT_FEAT * HID];        // Wm^T hi       [256][128]
__device__ __half g_W2tl[OUT_FEAT * HID];        // Wm^T lo
__device__ float  g_hb  [HID];                   // b_node + b_edge
// CSR-by-dst
__device__ int    g_cnt [N_NODES];               // histogram, then cursor
__device__ int    g_off [N_NODES + 1];
__device__ int2   g_edge[N_EDGES];               // {src, w_bits}

// ---------------------------------------------------------------------------
// helpers
// ---------------------------------------------------------------------------
__device__ __forceinline__ void split_h(float v, __half& hi, __half& lo) {
    hi = __float2half_rn(v);
    lo = __float2half_rn(v - __half2float(hi));
}
__device__ __forceinline__ uint32_t packh(__half a, __half b) {
    __half2 h2 = __halves2half2(a, b);
    return *(uint32_t*)&h2;
}
__device__ __forceinline__ uint32_t smem_u32(const void* p) {
    uint32_t a;
    asm("{ .reg .u64 t; cvta.to.shared.u64 t, %1; cvt.u32.u64 %0, t; }"
        : "=r"(a) : "l"(p));
    return a;
}
#define CP_ASYNC16(dst, src, sz) \
    asm volatile("cp.async.cg.shared.global [%0], [%1], 16, %2;" \
                 :: "r"(dst), "l"(src), "r"(sz) : "memory")
#define CP_COMMIT()  asm volatile("cp.async.commit_group;" ::: "memory")
#define CP_WAIT1()   asm volatile("cp.async.wait_group 1;"  ::: "memory")

// ---------------------------------------------------------------------------
// CSR build: zero -> hist -> scan -> scatter
// ---------------------------------------------------------------------------
__global__ void zero_cnt_kernel() {
    int i = blockIdx.x * blockDim.x + threadIdx.x;
    if (i < N_NODES) g_cnt[i] = 0;
}

__global__ void hist_kernel(const int* __restrict__ dst) {
    int e = blockIdx.x * blockDim.x + threadIdx.x;
    if (e < N_EDGES) atomicAdd(&g_cnt[dst[e]], 1);
}

__global__ __launch_bounds__(1024) void scan_kernel() {
    __shared__ int part[1024];
    const int tid = threadIdx.x;
    const int C = (N_NODES + 1023) / 1024;          // 49
    const int base = tid * C;
    int s = 0;
    for (int j = 0; j < C; ++j) {
        int i = base + j;
        if (i < N_NODES) s += g_cnt[i];
    }
    part[tid] = s;
    __syncthreads();
    for (int d = 1; d < 1024; d <<= 1) {            // Hillis-Steele inclusive
        int v = 0;
        if (tid >= d) v = part[tid - d];
        __syncthreads();
        if (tid >= d) part[tid] += v;
        __syncthreads();
    }
    int run = (tid == 0) ? 0 : part[tid - 1];
    for (int j = 0; j < C; ++j) {
        int i = base + j;
        if (i < N_NODES) {
            int c = g_cnt[i];
            g_off[i] = run;
            g_cnt[i] = run;                          // cursor for scatter
            run += c;
        }
    }
    if (tid == 0) g_off[N_NODES] = part[1023];
}

__global__ void scatter_kernel(const int* __restrict__ src,
                               const int* __restrict__ dst,
                               const float* __restrict__ w) {
    int e = blockIdx.x * blockDim.x + threadIdx.x;
    if (e >= N_EDGES) return;
    int d = dst[e];
    int p = atomicAdd(&g_cnt[d], 1);
    g_edge[p] = make_int2(src[e], __float_as_int(w[e]));
}

// ---------------------------------------------------------------------------
// pre-split x into fp16 hi/lo
// ---------------------------------------------------------------------------
__global__ void split_x_kernel(const float4* __restrict__ x4) {
    int i = blockIdx.x * blockDim.x + threadIdx.x;
    if (i >= N_NODES * IN_FEAT / 4) return;
    float4 v = x4[i];
    __half h0, l0, h1, l1, h2, l2, h3, l3;
    split_h(v.x, h0, l0); split_h(v.y, h1, l1);
    split_h(v.z, h2, l2); split_h(v.w, h3, l3);
    uint2 H = make_uint2(packh(h0, h1), packh(h2, h3));
    uint2 L = make_uint2(packh(l0, l1), packh(l2, l3));
    *(uint2*)&g_xh[i * 4] = H;
    *(uint2*)&g_xl[i * 4] = L;
}

// ---------------------------------------------------------------------------
// fused weight transposes (fp16-split)
//   idx in [0, 65536):           W1t[n][k] = n<128 ? We[k][n] : Wn[k][n-128]
//   idx in [65536, 98304):       W2t[n][k] = Wm[k][n]
//   idx < 128:                   hb[idx]   = bn + be
// ---------------------------------------------------------------------------
__global__ void fold_weights_kernel(const float* __restrict__ We,
                                    const float* __restrict__ Wn,
                                    const float* __restrict__ Wm,
                                    const float* __restrict__ bn,
                                    const float* __restrict__ be) {
    int idx = blockIdx.x * blockDim.x + threadIdx.x;
    if (idx < N_YZ * IN_FEAT) {
        int n = idx >> 8;            // 0..255
        int k = idx & 255;           // 0..255
        float v = (n < HID) ? We[(size_t)k * HID + n]
                            : Wn[(size_t)k * HID + (n - HID)];
        __half h, l;
        split_h(v, h, l);
        g_W1th[(size_t)n * IN_FEAT + k] = h;
        g_W1tl[(size_t)n * IN_FEAT + k] = l;
    } else if (idx < N_YZ * IN_FEAT + OUT_FEAT * HID) {
        int r = idx - N_YZ * IN_FEAT;
        int n = r >> 7;              // 0..255
        int k = r & 127;             // 0..127
        float v = Wm[(size_t)k * OUT_FEAT + n];
        __half h, l;
        split_h(v, h, l);
        g_W2th[(size_t)n * HID + k] = h;
        g_W2tl[(size_t)n * HID + k] = l;
    }
    if (idx < HID) g_hb[idx] = bn[idx] + be[idx];
}

// ---------------------------------------------------------------------------
// CSR aggregation + h fusion: one warp per node, no atomics.
//   h[v] = z[v] + sum_e y[src_e]*w_e + hb ;  output split fp16 hi/lo
// y is fp16: a row = 128 halfs = 256 B = 16 x uint4. Half-warps (16 lanes x
// 16B LDG.128) process alternating edges; 2-edge unroll gives MLP=2 per
// half-warp; one shfl_xor(16) merges the halves.
// ---------------------------------------------------------------------------
__global__ __launch_bounds__(256) void agg_csr_kernel() {
    int v    = (blockIdx.x * blockDim.x + threadIdx.x) >> 5;
    int lane = threadIdx.x & 31;
    if (v >= N_NODES) return;

    const int half_id = lane >> 4;       // 0 or 1
    const int l16     = lane & 15;       // covers cols l16*8 .. l16*8+7

    int b  = g_off[v];
    int e2 = g_off[v + 1];
    const uint4* yb = (const uint4*)g_y16;   // 16 uint4 per row

    float acc0[8], acc1[8];
    #pragma unroll
    for (int j = 0; j < 8; ++j) { acc0[j] = 0.f; acc1[j] = 0.f; }

    int i = b + half_id;
    // unrolled: edges i and i+2 in flight simultaneously
    for (; i + 2 < e2; i += 4) {
        int2 ea = g_edge[i];
        int2 eb = g_edge[i + 2];
        float wa = __int_as_float(ea.y);
        float wb = __int_as_float(eb.y);
        uint4 qa = yb[(size_t)ea.x * 16 + l16];
        uint4 qb = yb[(size_t)eb.x * 16 + l16];
        {
            float2 f0 = __half22float2(*(const __half2*)&qa.x);
            float2 f1 = __half22float2(*((const __half2*)&qa.x + 1));
            float2 f2 = __half22float2(*(const __half2*)&qa.z);
            float2 f3 = __half22float2(*((const __half2*)&qa.z + 1));
            acc0[0] = fmaf(f0.x, wa, acc0[0]);
            acc0[1] = fmaf(f0.y, wa, acc0[1]);
            acc0[2] = fmaf(f1.x, wa, acc0[2]);
            acc0[3] = fmaf(f1.y, wa, acc0[3]);
            acc0[4] = fmaf(f2.x, wa, acc0[4]);
            acc0[5] = fmaf(f2.y, wa, acc0[5]);
            acc0[6] = fmaf(f3.x, wa, acc0[6]);
            acc0[7] = fmaf(f3.y, wa, acc0[7]);
        }
        {
            float2 f0 = __half22float2(*(const __half2*)&qb.x);
            float2 f1 = __half22float2(*((const __half2*)&qb.x + 1));
            float2 f2 = __half22float2(*(const __half2*)&qb.z);
            float2 f3 = __half22float2(*((const __half2*)&qb.z + 1));
            acc1[0] = fmaf(f0.x, wb, acc1[0]);
            acc1[1] = fmaf(f0.y, wb, acc1[1]);
            acc1[2] = fmaf(f1.x, wb, acc1[2]);
            acc1[3] = fmaf(f1.y, wb, acc1[3]);
            acc1[4] = fmaf(f2.x, wb, acc1[4]);
            acc1[5] = fmaf(f2.y, wb, acc1[5]);
            acc1[6] = fmaf(f3.x, wb, acc1[6]);
            acc1[7] = fmaf(f3.y, wb, acc1[7]);
        }
    }
    // tail
    for (; i < e2; i += 2) {
        int2 e = g_edge[i];
        float wgt = __int_as_float(e.y);
        uint4 q = yb[(size_t)e.x * 16 + l16];
        float2 f0 = __half22float2(*(const __half2*)&q.x);
        float2 f1 = __half22float2(*((const __half2*)&q.x + 1));
        float2 f2 = __half22float2(*(const __half2*)&q.z);
        float2 f3 = __half22float2(*((const __half2*)&q.z + 1));
        acc0[0] = fmaf(f0.x, wgt, acc0[0]);
        acc0[1] = fmaf(f0.y, wgt, acc0[1]);
        acc0[2] = fmaf(f1.x, wgt, acc0[2]);
        acc0[3] = fmaf(f1.y, wgt, acc0[3]);
        acc0[4] = fmaf(f2.x, wgt, acc0[4]);
        acc0[5] = fmaf(f2.y, wgt, acc0[5]);
        acc0[6] = fmaf(f3.x, wgt, acc0[6]);
        acc0[7] = fmaf(f3.y, wgt, acc0[7]);
    }

    float acc[8];
    #pragma unroll
    for (int j = 0; j < 8; ++j) acc[j] = acc0[j] + acc1[j];

    // merge the two half-warp partial sums
    #pragma unroll
    for (int j = 0; j < 8; ++j)
        acc[j] += __shfl_xor_sync(0xffffffffu, acc[j], 16);

    // add z + hb for cols l16*8 .. +7
    const float4* zp  = (const float4*)(g_z  + (size_t)v * HID + l16 * 8);
    const float4* hbp = (const float4*)(g_hb + l16 * 8);
    float4 z0 = zp[0],  z1 = zp[1];
    float4 h0 = hbp[0], h1 = hbp[1];
    acc[0] += z0.x + h0.x;  acc[1] += z0.y + h0.y;
    acc[2] += z0.z + h0.z;  acc[3] += z0.w + h0.w;
    acc[4] += z1.x + h1.x;  acc[5] += z1.y + h1.y;
    acc[6] += z1.z + h1.z;  acc[7] += z1.w + h1.w;

    // split and store: half 0 writes hi, half 1 writes lo (both have full sums)
    __half hs[8], ls[8];
    #pragma unroll
    for (int j = 0; j < 8; ++j) split_h(acc[j], hs[j], ls[j]);
    uint4 pkt;
    if (half_id == 0) {
        pkt.x = packh(hs[0], hs[1]); pkt.y = packh(hs[2], hs[3]);
        pkt.z = packh(hs[4], hs[5]); pkt.w = packh(hs[6], hs[7]);
    } else {
        pkt.x = packh(ls[0], ls[1]); pkt.y = packh(ls[2], ls[3]);
        pkt.z = packh(ls[4], ls[5]); pkt.w = packh(ls[6], ls[7]);
    }
    __half* base = half_id ? g_hl : g_hh;
    *(uint4*)(base + (size_t)v * HID + l16 * 8) = pkt;
}

// ---------------------------------------------------------------------------
// split-precision fp16 GEMM, cp.async double-buffered (R9/R11-validated core).
// C = A @ Bt^T (+ bias); A,Bt pre-split fp16; A row stride = KTOT.
// YZ variant: column-block 0 writes fp16 y, block 1 writes fp32 z (stride HID).
// BM=128, BN=128, BK=32; 256 threads; warp tile 32x64; mma.m16n8k16.
// ---------------------------------------------------------------------------
#define MMA_F16(C, A, B0, B1)                                               \
    asm volatile(                                                           \
        "mma.sync.aligned.m16n8k16.row.col.f32.f16.f16.f32 "                \
        "{%0,%1,%2,%3}, {%4,%5,%6,%7}, {%8,%9}, {%0,%1,%2,%3};"             \
        : "+f"((C)[0]), "+f"((C)[1]), "+f"((C)[2]), "+f"((C)[3])            \
        : "r"((A)[0]), "r"((A)[1]), "r"((A)[2]), "r"((A)[3]),               \
          "r"(B0), "r"(B1))

#define STAGE_BYTES 40960
#define GEMM_SMEM   (2 * STAGE_BYTES)

template<int KTOT, int NOUT, bool BIAS, bool YZ>
__global__ __launch_bounds__(256) void gemm_f16_kernel(
    const __half* __restrict__ Ah, const __half* __restrict__ Al,   // [M x KTOT]
    const __half* __restrict__ Bh, const __half* __restrict__ Bl,   // [NOUT x KTOT]
    const float*  __restrict__ bias,
    float*        __restrict__ Cf,     // fp32 out (or z when YZ)
    __half*       __restrict__ Ch,     // fp16 y out (YZ only)
    int M) {
    extern __shared__ uint32_t sm[];
    const uint32_t smb = smem_u32(sm);

    const int tid  = threadIdx.x;
    const int brow = blockIdx.y * 128;
    const int bcol = blockIdx.x * 128;

    const int warp = tid >> 5, lane = tid & 31;
    const int g = lane >> 2, tg = lane & 3;
    const int wm = warp >> 1, wn = warp & 1;

    constexpr int T = KTOT / 32;

    float acc[2][8][4];
    #pragma unroll
    for (int mt = 0; mt < 2; ++mt)
        #pragma unroll
        for (int nt = 0; nt < 8; ++nt)
            #pragma unroll
            for (int i = 0; i < 4; ++i) acc[mt][nt][i] = 0.f;

    auto issue = [&](int t) {
        const int s  = t & 1;
        const uint32_t sb = smb + s * STAGE_BYTES;
        const int k0 = t * 32;
        #pragma unroll
        for (int i = 0; i < 2; ++i) {
            int ch = tid + i * 256;       // 0..511
            int m = ch >> 2, c = ch & 3;
            // ---- A ----
            int r = brow + m;
            uint32_t sz = (r < M) ? 16u : 0u;
            int rc = (r < M) ? r : (M - 1);
            size_t oa = (size_t)rc * KTOT + k0 + c * 8;
            uint32_t da = sb + (uint32_t)(m * 20 + c * 4) * 4;
            CP_ASYNC16(da,          Ah + oa, sz);
            CP_ASYNC16(da + 10240,  Al + oa, sz);
            // ---- B ----
            int n = bcol + m;
            size_t ob = (size_t)n * KTOT + k0 + c * 8;
            CP_ASYNC16(da + 20480, Bh + ob, 16u);
            CP_ASYNC16(da + 30720, Bl + ob, 16u);
        }
    };

    issue(0); CP_COMMIT();
    if (T > 1) issue(1);
    CP_COMMIT();

    for (int t = 0; t < T; ++t) {
        CP_WAIT1();
        __syncthreads();

        const uint32_t* Ash = sm + (t & 1) * (STAGE_BYTES / 4);
        const uint32_t* Asl = Ash + 2560;
        const uint32_t* Bsh = Ash + 5120;
        const uint32_t* Bsl = Ash + 7680;

        #pragma unroll
        for (int ks2 = 0; ks2 < 2; ++ks2) {
            const int kb = ks2 * 8;
            uint32_t afh[2][4], afl[2][4];
            #pragma unroll
            for (int mt = 0; mt < 2; ++mt) {
                int m0 = wm * 32 + mt * 16 + g;
                int o00 = m0 * 20 + kb + tg;
                int o10 = (m0 + 8) * 20 + kb + tg;
                afh[mt][0] = Ash[o00];     afl[mt][0] = Asl[o00];
                afh[mt][1] = Ash[o10];     afl[mt][1] = Asl[o10];
                afh[mt][2] = Ash[o00 + 4]; afl[mt][2] = Asl[o00 + 4];
                afh[mt][3] = Ash[o10 + 4]; afl[mt][3] = Asl[o10 + 4];
            }
            #pragma unroll
            for (int nt = 0; nt < 8; ++nt) {
                int n = wn * 64 + nt * 8 + g;
                int ob = n * 20 + kb + tg;
                uint32_t bh0 = Bsh[ob], bh1 = Bsh[ob + 4];
                uint32_t bl0 = Bsl[ob], bl1 = Bsl[ob + 4];
                #pragma unroll
                for (int mt = 0; mt < 2; ++mt) {
                    MMA_F16(acc[mt][nt], afh[mt], bh0, bh1);
                    MMA_F16(acc[mt][nt], afl[mt], bh0, bh1);
                    MMA_F16(acc[mt][nt], afh[mt], bl0, bl1);
                }
            }
        }
        __syncthreads();
        if (t + 2 < T) issue(t + 2);
        CP_COMMIT();
    }

    // ---- epilogue ----
    const bool y_block = YZ && (blockIdx.x == 0);
    #pragma unroll
    for (int mt = 0; mt < 2; ++mt) {
        int row0 = brow + wm * 32 + mt * 16 + g;
        int row1 = row0 + 8;
        #pragma unroll
        for (int nt = 0; nt < 8; ++nt) {
            int lcol = wn * 64 + nt * 8 + tg * 2;        // 0..127 within block
            if (y_block) {
                if (row0 < M)
                    *(__half2*)(Ch + (size_t)row0 * HID + lcol) =
                        __floats2half2_rn(acc[mt][nt][0], acc[mt][nt][1]);
                if (row1 < M)
                    *(__half2*)(Ch + (size_t)row1 * HID + lcol) =
                        __floats2half2_rn(acc[mt][nt][2], acc[mt][nt][3]);
            } else {
                const int stride = YZ ? HID : NOUT;       // z stride = HID
                const int col    = YZ ? lcol : (bcol + lcol);
                float b0 = BIAS ? bias[col]     : 0.f;
                float b1 = BIAS ? bias[col + 1] : 0.f;
                if (row0 < M) {
                    float2 o = make_float2(acc[mt][nt][0] + b0, acc[mt][nt][1] + b1);
                    *(float2*)(Cf + (size_t)row0 * stride + col) = o;
                }
                if (row1 < M) {
                    float2 o = make_float2(acc[mt][nt][2] + b0, acc[mt][nt][3] + b1);
                    *(float2*)(Cf + (size_t)row1 * stride + col) = o;
                }
            }
        }
    }
}

// ---------------------------------------------------------------------------
// launch — side stream: split_x then CSR build; main: folds then GEMM1.
// GEMM1 waits on split_x event; agg waits on CSR join event.
// Streams/events are host objects, created per call and intentionally not
// destroyed (cannot destroy a capturing stream inside the capture region).
// ---------------------------------------------------------------------------
extern "C" void kernel_launch(void* const* d_in, const int* in_sizes, int n_in,
                              void* d_out, int out_size) {
    const float* x   = (const float*)d_in[0];
    const float* w   = (const float*)d_in[1];
    const int*   src = (const int*)  d_in[2];
    const int*   dst = (const int*)  d_in[3];
    const float* Wn  = (const float*)d_in[4];
    const float* bn  = (const float*)d_in[5];
    const float* We  = (const float*)d_in[6];
    const float* be  = (const float*)d_in[7];
    const float* Wm  = (const float*)d_in[8];
    const float* bm  = (const float*)d_in[9];
    float*       out = (float*)d_out;

    float *z;
    __half *y16, *xh, *xl, *hh, *hl, *W1th, *W1tl, *W2th, *W2tl;
    cudaGetSymbolAddress((void**)&y16,  g_y16);
    cudaGetSymbolAddress((void**)&z,    g_z);
    cudaGetSymbolAddress((void**)&xh,   g_xh);
    cudaGetSymbolAddress((void**)&xl,   g_xl);
    cudaGetSymbolAddress((void**)&hh,   g_hh);
    cudaGetSymbolAddress((void**)&hl,   g_hl);
    cudaGetSymbolAddress((void**)&W1th, g_W1th);
    cudaGetSymbolAddress((void**)&W1tl, g_W1tl);
    cudaGetSymbolAddress((void**)&W2th, g_W2th);
    cudaGetSymbolAddress((void**)&W2tl, g_W2tl);

    cudaFuncSetAttribute(gemm_f16_kernel<IN_FEAT, N_YZ, false, true>,
                         cudaFuncAttributeMaxDynamicSharedMemorySize, GEMM_SMEM);
    cudaFuncSetAttribute(gemm_f16_kernel<HID, OUT_FEAT, true, false>,
                         cudaFuncAttributeMaxDynamicSharedMemorySize, GEMM_SMEM);

    // fork resources (created per call; see header comment)
    cudaStream_t s2;
    cudaStreamCreateWithFlags(&s2, cudaStreamNonBlocking);
    cudaEvent_t eFork, eSplit, eJoin;
    cudaEventCreateWithFlags(&eFork,  cudaEventDisableTiming);
    cudaEventCreateWithFlags(&eSplit, cudaEventDisableTiming);
    cudaEventCreateWithFlags(&eJoin,  cudaEventDisableTiming);

    // ---- fork: split_x then CSR build on side stream ----
    cudaEventRecord(eFork, 0);
    cudaStreamWaitEvent(s2, eFork, 0);
    split_x_kernel<<<(N_NODES * IN_FEAT / 4 + 255) / 256, 256, 0, s2>>>(
        (const float4*)x);
    cudaEventRecord(eSplit, s2);
    zero_cnt_kernel<<<(N_NODES + 255) / 256, 256, 0, s2>>>();
    hist_kernel<<<(N_EDGES + 255) / 256, 256, 0, s2>>>(dst);
    scan_kernel<<<1, 1024, 0, s2>>>();
    scatter_kernel<<<(N_EDGES + 255) / 256, 256, 0, s2>>>(src, dst, w);
    cudaEventRecord(eJoin, s2);

    // ---- dense chain on main stream ----
    {
        int total = N_YZ * IN_FEAT + OUT_FEAT * HID;   // 98304
        fold_weights_kernel<<<(total + 255) / 256, 256>>>(We, Wn, Wm, bn, be);
    }
    cudaStreamWaitEvent(0, eSplit, 0);   // GEMM1 reads xh/xl

    // GEMM1: [y|z] = x @ [We|Wn];  y -> fp16, z -> fp32
    {
        dim3 grid(N_YZ / 128, (N_NODES + 127) / 128);
        gemm_f16_kernel<IN_FEAT, N_YZ, false, true>
            <<<grid, 256, GEMM_SMEM>>>(xh, xl, W1th, W1tl, nullptr, z, y16, N_NODES);
    }

    // ---- join: agg needs CSR + GEMM1 ----
    cudaStreamWaitEvent(0, eJoin, 0);

    // agg: h = z + sum y[src]*w + (bn+be)  -> split fp16
    agg_csr_kernel<<<(N_NODES * 32 + 255) / 256, 256>>>();

    // GEMM2: out = h @ Wm + bm   [50000 x 256] fp32
    {
        dim3 grid(OUT_FEAT / 128, (N_NODES + 127) / 128);
        gemm_f16_kernel<HID, OUT_FEAT, true, false>
            <<<grid, 256, GEMM_SMEM>>>(hh, hl, W2th, W2tl, bm, out, nullptr, N_NODES);
    }
}

// round 17
// speedup vs baseline: 1.2819x; 1.2819x over previous
#include <cuda_runtime.h>
#include <cuda_fp16.h>
#include <cstdint>

#define N_NODES  50000
#define N_EDGES  1600000
#define IN_FEAT  256
#define HID      128
#define OUT_FEAT 256
#define N_YZ     256              // [y | z] width

// ---------------------------------------------------------------------------
// Device scratch
// ---------------------------------------------------------------------------
__device__ __half g_y16 [N_NODES * HID];         // y fp16 (12.8 MB)
__device__ float  g_z   [N_NODES * HID];         // z fp32 (25.6 MB)
__device__ __half g_xh  [N_NODES * IN_FEAT];     // x split hi
__device__ __half g_xl  [N_NODES * IN_FEAT];     // x split lo
__device__ __half g_hh  [N_NODES * HID];         // h split hi
__device__ __half g_hl  [N_NODES * HID];         // h split lo
__device__ __half g_W1th[N_YZ * IN_FEAT];        // [We|Wn]^T hi  [256][256]
__device__ __half g_W1tl[N_YZ * IN_FEAT];        // [We|Wn]^T lo
__device__ __half g_W2th[OUT_FEAT * HID];        // Wm^T hi       [256][128]
__device__ __half g_W2tl[OUT_FEAT * HID];        // Wm^T lo
__device__ float  g_hb  [HID];                   // b_node + b_edge
// CSR-by-dst
__device__ int    g_cnt [N_NODES];               // histogram, then cursor
__device__ int    g_off [N_NODES + 1];
__device__ int2   g_edge[N_EDGES];               // {src, w_bits}

// ---------------------------------------------------------------------------
// helpers
// ---------------------------------------------------------------------------
__device__ __forceinline__ void split_h(float v, __half& hi, __half& lo) {
    hi = __float2half_rn(v);
    lo = __float2half_rn(v - __half2float(hi));
}
__device__ __forceinline__ uint32_t packh(__half a, __half b) {
    __half2 h2 = __halves2half2(a, b);
    return *(uint32_t*)&h2;
}
__device__ __forceinline__ uint32_t smem_u32(const void* p) {
    uint32_t a;
    asm("{ .reg .u64 t; cvta.to.shared.u64 t, %1; cvt.u32.u64 %0, t; }"
        : "=r"(a) : "l"(p));
    return a;
}
#define CP_ASYNC16(dst, src, sz) \
    asm volatile("cp.async.cg.shared.global [%0], [%1], 16, %2;" \
                 :: "r"(dst), "l"(src), "r"(sz) : "memory")
#define CP_COMMIT()  asm volatile("cp.async.commit_group;" ::: "memory")
#define CP_WAIT1()   asm volatile("cp.async.wait_group 1;"  ::: "memory")

// ---------------------------------------------------------------------------
// CSR build: zero -> hist -> scan -> scatter
// ---------------------------------------------------------------------------
__global__ void zero_cnt_kernel() {
    int i = blockIdx.x * blockDim.x + threadIdx.x;
    if (i < N_NODES) g_cnt[i] = 0;
}

__global__ void hist_kernel(const int* __restrict__ dst) {
    int e = blockIdx.x * blockDim.x + threadIdx.x;
    if (e < N_EDGES) atomicAdd(&g_cnt[dst[e]], 1);
}

// Contention-hardened single-block scan: each thread caches its 49 counts in
// registers via an unrolled guarded load burst (MLP=49), so inflated L2
// latency under concurrent GEMM traffic is paid once, not 98 times.
#define SCAN_C 49
__global__ __launch_bounds__(1024) void scan_kernel() {
    __shared__ int part[1024];
    const int tid  = threadIdx.x;
    const int base = tid * SCAN_C;

    int vals[SCAN_C];
    #pragma unroll
    for (int j = 0; j < SCAN_C; ++j) {
        int i = base + j;
        vals[j] = (i < N_NODES) ? g_cnt[i] : 0;
    }
    int s = 0;
    #pragma unroll
    for (int j = 0; j < SCAN_C; ++j) s += vals[j];

    part[tid] = s;
    __syncthreads();
    for (int d = 1; d < 1024; d <<= 1) {            // Hillis-Steele inclusive
        int v = 0;
        if (tid >= d) v = part[tid - d];
        __syncthreads();
        if (tid >= d) part[tid] += v;
        __syncthreads();
    }
    int run = (tid == 0) ? 0 : part[tid - 1];
    #pragma unroll
    for (int j = 0; j < SCAN_C; ++j) {
        int i = base + j;
        if (i < N_NODES) {
            g_off[i] = run;
            g_cnt[i] = run;                          // cursor for scatter
            run += vals[j];
        }
    }
    if (tid == 1023) g_off[N_NODES] = part[1023];
}

__global__ void scatter_kernel(const int* __restrict__ src,
                               const int* __restrict__ dst,
                               const float* __restrict__ w) {
    int e = blockIdx.x * blockDim.x + threadIdx.x;
    if (e >= N_EDGES) return;
    int d = dst[e];
    int p = atomicAdd(&g_cnt[d], 1);
    g_edge[p] = make_int2(src[e], __float_as_int(w[e]));
}

// ---------------------------------------------------------------------------
// pre-split x into fp16 hi/lo
// ---------------------------------------------------------------------------
__global__ void split_x_kernel(const float4* __restrict__ x4) {
    int i = blockIdx.x * blockDim.x + threadIdx.x;
    if (i >= N_NODES * IN_FEAT / 4) return;
    float4 v = x4[i];
    __half h0, l0, h1, l1, h2, l2, h3, l3;
    split_h(v.x, h0, l0); split_h(v.y, h1, l1);
    split_h(v.z, h2, l2); split_h(v.w, h3, l3);
    uint2 H = make_uint2(packh(h0, h1), packh(h2, h3));
    uint2 L = make_uint2(packh(l0, l1), packh(l2, l3));
    *(uint2*)&g_xh[i * 4] = H;
    *(uint2*)&g_xl[i * 4] = L;
}

// ---------------------------------------------------------------------------
// fused weight transposes (fp16-split)
// ---------------------------------------------------------------------------
__global__ void fold_weights_kernel(const float* __restrict__ We,
                                    const float* __restrict__ Wn,
                                    const float* __restrict__ Wm,
                                    const float* __restrict__ bn,
                                    const float* __restrict__ be) {
    int idx = blockIdx.x * blockDim.x + threadIdx.x;
    if (idx < N_YZ * IN_FEAT) {
        int n = idx >> 8;            // 0..255
        int k = idx & 255;           // 0..255
        float v = (n < HID) ? We[(size_t)k * HID + n]
                            : Wn[(size_t)k * HID + (n - HID)];
        __half h, l;
        split_h(v, h, l);
        g_W1th[(size_t)n * IN_FEAT + k] = h;
        g_W1tl[(size_t)n * IN_FEAT + k] = l;
    } else if (idx < N_YZ * IN_FEAT + OUT_FEAT * HID) {
        int r = idx - N_YZ * IN_FEAT;
        int n = r >> 7;              // 0..255
        int k = r & 127;             // 0..127
        float v = Wm[(size_t)k * OUT_FEAT + n];
        __half h, l;
        split_h(v, h, l);
        g_W2th[(size_t)n * HID + k] = h;
        g_W2tl[(size_t)n * HID + k] = l;
    }
    if (idx < HID) g_hb[idx] = bn[idx] + be[idx];
}

// ---------------------------------------------------------------------------
// CSR aggregation + h fusion: one warp per node, no atomics.
//   h[v] = z[v] + sum_e y[src_e]*w_e + hb ;  output split fp16 hi/lo
// Half-warps (16 lanes x 16B LDG.128) process alternating edges; 2-edge
// unroll gives MLP=2 per half-warp; one shfl_xor(16) merges the halves.
// ---------------------------------------------------------------------------
__global__ __launch_bounds__(256) void agg_csr_kernel() {
    int v    = (blockIdx.x * blockDim.x + threadIdx.x) >> 5;
    int lane = threadIdx.x & 31;
    if (v >= N_NODES) return;

    const int half_id = lane >> 4;       // 0 or 1
    const int l16     = lane & 15;       // covers cols l16*8 .. l16*8+7

    int b  = g_off[v];
    int e2 = g_off[v + 1];
    const uint4* yb = (const uint4*)g_y16;   // 16 uint4 per row

    float acc0[8], acc1[8];
    #pragma unroll
    for (int j = 0; j < 8; ++j) { acc0[j] = 0.f; acc1[j] = 0.f; }

    int i = b + half_id;
    for (; i + 2 < e2; i += 4) {
        int2 ea = g_edge[i];
        int2 eb = g_edge[i + 2];
        float wa = __int_as_float(ea.y);
        float wb = __int_as_float(eb.y);
        uint4 qa = yb[(size_t)ea.x * 16 + l16];
        uint4 qb = yb[(size_t)eb.x * 16 + l16];
        {
            float2 f0 = __half22float2(*(const __half2*)&qa.x);
            float2 f1 = __half22float2(*((const __half2*)&qa.x + 1));
            float2 f2 = __half22float2(*(const __half2*)&qa.z);
            float2 f3 = __half22float2(*((const __half2*)&qa.z + 1));
            acc0[0] = fmaf(f0.x, wa, acc0[0]);
            acc0[1] = fmaf(f0.y, wa, acc0[1]);
            acc0[2] = fmaf(f1.x, wa, acc0[2]);
            acc0[3] = fmaf(f1.y, wa, acc0[3]);
            acc0[4] = fmaf(f2.x, wa, acc0[4]);
            acc0[5] = fmaf(f2.y, wa, acc0[5]);
            acc0[6] = fmaf(f3.x, wa, acc0[6]);
            acc0[7] = fmaf(f3.y, wa, acc0[7]);
        }
        {
            float2 f0 = __half22float2(*(const __half2*)&qb.x);
            float2 f1 = __half22float2(*((const __half2*)&qb.x + 1));
            float2 f2 = __half22float2(*(const __half2*)&qb.z);
            float2 f3 = __half22float2(*((const __half2*)&qb.z + 1));
            acc1[0] = fmaf(f0.x, wb, acc1[0]);
            acc1[1] = fmaf(f0.y, wb, acc1[1]);
            acc1[2] = fmaf(f1.x, wb, acc1[2]);
            acc1[3] = fmaf(f1.y, wb, acc1[3]);
            acc1[4] = fmaf(f2.x, wb, acc1[4]);
            acc1[5] = fmaf(f2.y, wb, acc1[5]);
            acc1[6] = fmaf(f3.x, wb, acc1[6]);
            acc1[7] = fmaf(f3.y, wb, acc1[7]);
        }
    }
    for (; i < e2; i += 2) {
        int2 e = g_edge[i];
        float wgt = __int_as_float(e.y);
        uint4 q = yb[(size_t)e.x * 16 + l16];
        float2 f0 = __half22float2(*(const __half2*)&q.x);
        float2 f1 = __half22float2(*((const __half2*)&q.x + 1));
        float2 f2 = __half22float2(*(const __half2*)&q.z);
        float2 f3 = __half22float2(*((const __half2*)&q.z + 1));
        acc0[0] = fmaf(f0.x, wgt, acc0[0]);
        acc0[1] = fmaf(f0.y, wgt, acc0[1]);
        acc0[2] = fmaf(f1.x, wgt, acc0[2]);
        acc0[3] = fmaf(f1.y, wgt, acc0[3]);
        acc0[4] = fmaf(f2.x, wgt, acc0[4]);
        acc0[5] = fmaf(f2.y, wgt, acc0[5]);
        acc0[6] = fmaf(f3.x, wgt, acc0[6]);
        acc0[7] = fmaf(f3.y, wgt, acc0[7]);
    }

    float acc[8];
    #pragma unroll
    for (int j = 0; j < 8; ++j) acc[j] = acc0[j] + acc1[j];

    #pragma unroll
    for (int j = 0; j < 8; ++j)
        acc[j] += __shfl_xor_sync(0xffffffffu, acc[j], 16);

    const float4* zp  = (const float4*)(g_z  + (size_t)v * HID + l16 * 8);
    const float4* hbp = (const float4*)(g_hb + l16 * 8);
    float4 z0 = zp[0],  z1 = zp[1];
    float4 h0 = hbp[0], h1 = hbp[1];
    acc[0] += z0.x + h0.x;  acc[1] += z0.y + h0.y;
    acc[2] += z0.z + h0.z;  acc[3] += z0.w + h0.w;
    acc[4] += z1.x + h1.x;  acc[5] += z1.y + h1.y;
    acc[6] += z1.z + h1.z;  acc[7] += z1.w + h1.w;

    __half hs[8], ls[8];
    #pragma unroll
    for (int j = 0; j < 8; ++j) split_h(acc[j], hs[j], ls[j]);
    uint4 pkt;
    if (half_id == 0) {
        pkt.x = packh(hs[0], hs[1]); pkt.y = packh(hs[2], hs[3]);
        pkt.z = packh(hs[4], hs[5]); pkt.w = packh(hs[6], hs[7]);
    } else {
        pkt.x = packh(ls[0], ls[1]); pkt.y = packh(ls[2], ls[3]);
        pkt.z = packh(ls[4], ls[5]); pkt.w = packh(ls[6], ls[7]);
    }
    __half* base = half_id ? g_hl : g_hh;
    *(uint4*)(base + (size_t)v * HID + l16 * 8) = pkt;
}

// ---------------------------------------------------------------------------
// split-precision fp16 GEMM, cp.async double-buffered (validated core).
// C = A @ Bt^T (+ bias); A,Bt pre-split fp16; A row stride = KTOT.
// YZ variant: column-block 0 writes fp16 y, block 1 writes fp32 z (stride HID).
// ---------------------------------------------------------------------------
#define MMA_F16(C, A, B0, B1)                                               \
    asm volatile(                                                           \
        "mma.sync.aligned.m16n8k16.row.col.f32.f16.f16.f32 "                \
        "{%0,%1,%2,%3}, {%4,%5,%6,%7}, {%8,%9}, {%0,%1,%2,%3};"             \
        : "+f"((C)[0]), "+f"((C)[1]), "+f"((C)[2]), "+f"((C)[3])            \
        : "r"((A)[0]), "r"((A)[1]), "r"((A)[2]), "r"((A)[3]),               \
          "r"(B0), "r"(B1))

#define STAGE_BYTES 40960
#define GEMM_SMEM   (2 * STAGE_BYTES)

template<int KTOT, int NOUT, bool BIAS, bool YZ>
__global__ __launch_bounds__(256) void gemm_f16_kernel(
    const __half* __restrict__ Ah, const __half* __restrict__ Al,   // [M x KTOT]
    const __half* __restrict__ Bh, const __half* __restrict__ Bl,   // [NOUT x KTOT]
    const float*  __restrict__ bias,
    float*        __restrict__ Cf,     // fp32 out (or z when YZ)
    __half*       __restrict__ Ch,     // fp16 y out (YZ only)
    int M) {
    extern __shared__ uint32_t sm[];
    const uint32_t smb = smem_u32(sm);

    const int tid  = threadIdx.x;
    const int brow = blockIdx.y * 128;
    const int bcol = blockIdx.x * 128;

    const int warp = tid >> 5, lane = tid & 31;
    const int g = lane >> 2, tg = lane & 3;
    const int wm = warp >> 1, wn = warp & 1;

    constexpr int T = KTOT / 32;

    float acc[2][8][4];
    #pragma unroll
    for (int mt = 0; mt < 2; ++mt)
        #pragma unroll
        for (int nt = 0; nt < 8; ++nt)
            #pragma unroll
            for (int i = 0; i < 4; ++i) acc[mt][nt][i] = 0.f;

    auto issue = [&](int t) {
        const int s  = t & 1;
        const uint32_t sb = smb + s * STAGE_BYTES;
        const int k0 = t * 32;
        #pragma unroll
        for (int i = 0; i < 2; ++i) {
            int ch = tid + i * 256;       // 0..511
            int m = ch >> 2, c = ch & 3;
            // ---- A ----
            int r = brow + m;
            uint32_t sz = (r < M) ? 16u : 0u;
            int rc = (r < M) ? r : (M - 1);
            size_t oa = (size_t)rc * KTOT + k0 + c * 8;
            uint32_t da = sb + (uint32_t)(m * 20 + c * 4) * 4;
            CP_ASYNC16(da,          Ah + oa, sz);
            CP_ASYNC16(da + 10240,  Al + oa, sz);
            // ---- B ----
            int n = bcol + m;
            size_t ob = (size_t)n * KTOT + k0 + c * 8;
            CP_ASYNC16(da + 20480, Bh + ob, 16u);
            CP_ASYNC16(da + 30720, Bl + ob, 16u);
        }
    };

    issue(0); CP_COMMIT();
    if (T > 1) issue(1);
    CP_COMMIT();

    for (int t = 0; t < T; ++t) {
        CP_WAIT1();
        __syncthreads();

        const uint32_t* Ash = sm + (t & 1) * (STAGE_BYTES / 4);
        const uint32_t* Asl = Ash + 2560;
        const uint32_t* Bsh = Ash + 5120;
        const uint32_t* Bsl = Ash + 7680;

        #pragma unroll
        for (int ks2 = 0; ks2 < 2; ++ks2) {
            const int kb = ks2 * 8;
            uint32_t afh[2][4], afl[2][4];
            #pragma unroll
            for (int mt = 0; mt < 2; ++mt) {
                int m0 = wm * 32 + mt * 16 + g;
                int o00 = m0 * 20 + kb + tg;
                int o10 = (m0 + 8) * 20 + kb + tg;
                afh[mt][0] = Ash[o00];     afl[mt][0] = Asl[o00];
                afh[mt][1] = Ash[o10];     afl[mt][1] = Asl[o10];
                afh[mt][2] = Ash[o00 + 4]; afl[mt][2] = Asl[o00 + 4];
                afh[mt][3] = Ash[o10 + 4]; afl[mt][3] = Asl[o10 + 4];
            }
            #pragma unroll
            for (int nt = 0; nt < 8; ++nt) {
                int n = wn * 64 + nt * 8 + g;
                int ob = n * 20 + kb + tg;
                uint32_t bh0 = Bsh[ob], bh1 = Bsh[ob + 4];
                uint32_t bl0 = Bsl[ob], bl1 = Bsl[ob + 4];
                #pragma unroll
                for (int mt = 0; mt < 2; ++mt) {
                    MMA_F16(acc[mt][nt], afh[mt], bh0, bh1);
                    MMA_F16(acc[mt][nt], afl[mt], bh0, bh1);
                    MMA_F16(acc[mt][nt], afh[mt], bl0, bl1);
                }
            }
        }
        __syncthreads();
        if (t + 2 < T) issue(t + 2);
        CP_COMMIT();
    }

    // ---- epilogue ----
    const bool y_block = YZ && (blockIdx.x == 0);
    #pragma unroll
    for (int mt = 0; mt < 2; ++mt) {
        int row0 = brow + wm * 32 + mt * 16 + g;
        int row1 = row0 + 8;
        #pragma unroll
        for (int nt = 0; nt < 8; ++nt) {
            int lcol = wn * 64 + nt * 8 + tg * 2;        // 0..127 within block
            if (y_block) {
                if (row0 < M)
                    *(__half2*)(Ch + (size_t)row0 * HID + lcol) =
                        __floats2half2_rn(acc[mt][nt][0], acc[mt][nt][1]);
                if (row1 < M)
                    *(__half2*)(Ch + (size_t)row1 * HID + lcol) =
                        __floats2half2_rn(acc[mt][nt][2], acc[mt][nt][3]);
            } else {
                const int stride = YZ ? HID : NOUT;       // z stride = HID
                const int col    = YZ ? lcol : (bcol + lcol);
                float b0 = BIAS ? bias[col]     : 0.f;
                float b1 = BIAS ? bias[col + 1] : 0.f;
                if (row0 < M) {
                    float2 o = make_float2(acc[mt][nt][0] + b0, acc[mt][nt][1] + b1);
                    *(float2*)(Cf + (size_t)row0 * stride + col) = o;
                }
                if (row1 < M) {
                    float2 o = make_float2(acc[mt][nt][2] + b0, acc[mt][nt][3] + b1);
                    *(float2*)(Cf + (size_t)row1 * stride + col) = o;
                }
            }
        }
    }
}

// ---------------------------------------------------------------------------
// launch — R14-proven topology: side stream = CSR chain only (starts at
// fork); main stream = split_x, folds, GEMM1; join before agg.
// Streams/events are host objects, created per call and intentionally not
// destroyed (cannot destroy a capturing stream inside the capture region).
// ---------------------------------------------------------------------------
extern "C" void kernel_launch(void* const* d_in, const int* in_sizes, int n_in,
                              void* d_out, int out_size) {
    const float* x   = (const float*)d_in[0];
    const float* w   = (const float*)d_in[1];
    const int*   src = (const int*)  d_in[2];
    const int*   dst = (const int*)  d_in[3];
    const float* Wn  = (const float*)d_in[4];
    const float* bn  = (const float*)d_in[5];
    const float* We  = (const float*)d_in[6];
    const float* be  = (const float*)d_in[7];
    const float* Wm  = (const float*)d_in[8];
    const float* bm  = (const float*)d_in[9];
    float*       out = (float*)d_out;

    float *z;
    __half *y16, *xh, *xl, *hh, *hl, *W1th, *W1tl, *W2th, *W2tl;
    cudaGetSymbolAddress((void**)&y16,  g_y16);
    cudaGetSymbolAddress((void**)&z,    g_z);
    cudaGetSymbolAddress((void**)&xh,   g_xh);
    cudaGetSymbolAddress((void**)&xl,   g_xl);
    cudaGetSymbolAddress((void**)&hh,   g_hh);
    cudaGetSymbolAddress((void**)&hl,   g_hl);
    cudaGetSymbolAddress((void**)&W1th, g_W1th);
    cudaGetSymbolAddress((void**)&W1tl, g_W1tl);
    cudaGetSymbolAddress((void**)&W2th, g_W2th);
    cudaGetSymbolAddress((void**)&W2tl, g_W2tl);

    cudaFuncSetAttribute(gemm_f16_kernel<IN_FEAT, N_YZ, false, true>,
                         cudaFuncAttributeMaxDynamicSharedMemorySize, GEMM_SMEM);
    cudaFuncSetAttribute(gemm_f16_kernel<HID, OUT_FEAT, true, false>,
                         cudaFuncAttributeMaxDynamicSharedMemorySize, GEMM_SMEM);

    // fork resources (created per call; see header comment)
    cudaStream_t s2;
    cudaStreamCreateWithFlags(&s2, cudaStreamNonBlocking);
    cudaEvent_t eFork, eJoin;
    cudaEventCreateWithFlags(&eFork, cudaEventDisableTiming);
    cudaEventCreateWithFlags(&eJoin, cudaEventDisableTiming);

    // ---- fork: CSR build on side stream (starts immediately) ----
    cudaEventRecord(eFork, 0);
    cudaStreamWaitEvent(s2, eFork, 0);
    zero_cnt_kernel<<<(N_NODES + 255) / 256, 256, 0, s2>>>();
    hist_kernel<<<(N_EDGES + 255) / 256, 256, 0, s2>>>(dst);
    scan_kernel<<<1, 1024, 0, s2>>>();
    scatter_kernel<<<(N_EDGES + 255) / 256, 256, 0, s2>>>(src, dst, w);
    cudaEventRecord(eJoin, s2);

    // ---- dense chain on main stream (overlaps CSR build) ----
    split_x_kernel<<<(N_NODES * IN_FEAT / 4 + 255) / 256, 256>>>((const float4*)x);
    {
        int total = N_YZ * IN_FEAT + OUT_FEAT * HID;   // 98304
        fold_weights_kernel<<<(total + 255) / 256, 256>>>(We, Wn, Wm, bn, be);
    }

    // GEMM1: [y|z] = x @ [We|Wn];  y -> fp16, z -> fp32
    {
        dim3 grid(N_YZ / 128, (N_NODES + 127) / 128);
        gemm_f16_kernel<IN_FEAT, N_YZ, false, true>
            <<<grid, 256, GEMM_SMEM>>>(xh, xl, W1th, W1tl, nullptr, z, y16, N_NODES);
    }

    // ---- join: agg needs CSR + GEMM1 ----
    cudaStreamWaitEvent(0, eJoin, 0);

    // agg: h = z + sum y[src]*w + (bn+be)  -> split fp16
    agg_csr_kernel<<<(N_NODES * 32 + 255) / 256, 256>>>();

    // GEMM2: out = h @ Wm + bm   [50000 x 256] fp32
    {
        dim3 grid(OUT_FEAT / 128, (N_NODES + 127) / 128);
        gemm_f16_kernel<HID, OUT_FEAT, true, false>
            <<<grid, 256, GEMM_SMEM>>>(hh, hl, W2th, W2tl, bm, out, nullptr, N_NODES);
    }
}